// round 6
// baseline (speedup 1.0000x reference)
#include <cuda_runtime.h>
#include <cuda_bf16.h>
#include <cstdint>

// Problem constants
#define NHEAD   8
#define DK      64
#define LEN     100
#define BS      32
#define DMODEL  512
#define TEMP    20.0f

// Pre-split normalized projections: [b][h][128 rows][64], bf16 packed in u32
// words (2 els/word -> 32 words/row). Rows 100..127 never written -> stay zero
// (static zero init) = free zero padding.
__device__ __align__(16) uint32_t g_Qhi[BS * NHEAD * 128 * 32];
__device__ __align__(16) uint32_t g_Qlo[BS * NHEAD * 128 * 32];
__device__ __align__(16) uint32_t g_Khi[BS * NHEAD * 128 * 32];
__device__ __align__(16) uint32_t g_Klo[BS * NHEAD * 128 * 32];
// V^T images per (kb,h): 64 d-rows x 60 words (words 0..55 = m pairs 0..111,
// m>=100 zero; words 56..59 zero pad). Exactly the smem image attn wants.
__device__ __align__(16) uint32_t g_Vhi[BS * NHEAD * 64 * 60];
__device__ __align__(16) uint32_t g_Vlo[BS * NHEAD * 64 * 60];

// ---------------------------------------------------------------------------
__device__ __forceinline__ void mma_bf16(float c[4],
    uint32_t a0, uint32_t a1, uint32_t a2, uint32_t a3,
    uint32_t b0, uint32_t b1)
{
    asm volatile(
        "mma.sync.aligned.m16n8k16.row.col.f32.bf16.bf16.f32 "
        "{%0,%1,%2,%3}, {%4,%5,%6,%7}, {%8,%9}, {%0,%1,%2,%3};"
        : "+f"(c[0]), "+f"(c[1]), "+f"(c[2]), "+f"(c[3])
        : "r"(a0), "r"(a1), "r"(a2), "r"(a3), "r"(b0), "r"(b1));
}

__device__ __forceinline__ void split2(float x0, float x1,
                                       uint32_t& hi, uint32_t& lo)
{
    __nv_bfloat16 h0 = __float2bfloat16(x0);
    __nv_bfloat16 h1 = __float2bfloat16(x1);
    float l0 = x0 - __bfloat162float(h0);
    float l1 = x1 - __bfloat162float(h1);
    __nv_bfloat162 hv; hv.x = h0; hv.y = h1;
    __nv_bfloat162 lv = __floats2bfloat162_rn(l0, l1);
    hi = *(uint32_t*)&hv;
    lo = *(uint32_t*)&lv;
}

// ---------------------------------------------------------------------------
// Kernel 1: projection via bf16 3-term mma + fused L2-norm, pre-split output.
// Block = (cb, b, sel): P rows b*100..+99 (pad 112), cols cb*64..+63, K=512.
// Raw-view head mapping: P-slab row r, band cb  ->  chunk n = r*8 + cb,
// logical head h = n/100, position l = n%100. Each slab row IS one chunk,
// so the per-row L2 normalize below normalizes exactly one (b,h,l) vector.
// ---------------------------------------------------------------------------
#define PJ_AHI 0                    // 112 x 36 words (stride 36 = 72 bf16)
#define PJ_ALO 16128
#define PJ_BHI 32256                // 64 x 36 words
#define PJ_BLO 41472
#define PJ_SMEM 50688               // S[112][68] fp32 (30464B) overlays A

__global__ __launch_bounds__(256) void proj_kernel(
    const float* __restrict__ q, const float* __restrict__ k,
    const float* __restrict__ w_qs, const float* __restrict__ w_ks)
{
    extern __shared__ char sm[];
    uint32_t* AHI = (uint32_t*)(sm + PJ_AHI);
    uint32_t* ALO = (uint32_t*)(sm + PJ_ALO);
    uint32_t* BHI = (uint32_t*)(sm + PJ_BHI);
    uint32_t* BLO = (uint32_t*)(sm + PJ_BLO);
    float* S = (float*)sm;          // overlay, used after mma done

    const int cb = blockIdx.x, b = blockIdx.y, sel = blockIdx.z;
    const float* x = sel ? k : q;
    const float* w = sel ? w_ks : w_qs;
    uint32_t* GH = sel ? g_Khi : g_Qhi;
    uint32_t* GL = sel ? g_Klo : g_Qlo;

    const int tid = threadIdx.x;
    const int warp = tid >> 5, lane = tid & 31;
    const int g = lane >> 2, t = lane & 3;

    float acc[7][4] = {};

    for (int c = 0; c < 8; c++) {
        // stage A chunk: 112 rows x 64 k (float4 grain), rows >=100 zero
        for (int i = tid; i < 112 * 16; i += 256) {
            const int r = i >> 4, c4 = i & 15;
            float4 a = (r < LEN)
                ? *(const float4*)(x + ((size_t)(b * 100 + r)) * DMODEL + c * 64 + c4 * 4)
                : make_float4(0.f, 0.f, 0.f, 0.f);
            uint32_t h0, l0, h1, l1;
            split2(a.x, a.y, h0, l0); split2(a.z, a.w, h1, l1);
            AHI[r * 36 + c4 * 2] = h0; AHI[r * 36 + c4 * 2 + 1] = h1;
            ALO[r * 36 + c4 * 2] = l0; ALO[r * 36 + c4 * 2 + 1] = l1;
        }
        // stage B chunk: 64 weight rows (cols cb*64..) x 64 k
        for (int i = tid; i < 64 * 16; i += 256) {
            const int r = i >> 4, c4 = i & 15;
            float4 a = *(const float4*)(w + ((size_t)(cb * 64 + r)) * DMODEL + c * 64 + c4 * 4);
            uint32_t h0, l0, h1, l1;
            split2(a.x, a.y, h0, l0); split2(a.z, a.w, h1, l1);
            BHI[r * 36 + c4 * 2] = h0; BHI[r * 36 + c4 * 2 + 1] = h1;
            BLO[r * 36 + c4 * 2] = l0; BLO[r * 36 + c4 * 2 + 1] = l1;
        }
        __syncthreads();

        #pragma unroll
        for (int ks = 0; ks < 4; ks++) {
            const int nb = (warp * 8 + g) * 36 + ks * 8 + t;
            const uint32_t bh0 = BHI[nb], bh1 = BHI[nb + 4];
            const uint32_t bl0 = BLO[nb], bl1 = BLO[nb + 4];
            #pragma unroll
            for (int i = 0; i < 7; i++) {
                const int rb = (i * 16 + g) * 36 + ks * 8 + t;
                const uint32_t ah0 = AHI[rb], ah1 = AHI[rb + 288];
                const uint32_t ah2 = AHI[rb + 4], ah3 = AHI[rb + 292];
                const uint32_t al0 = ALO[rb], al1 = ALO[rb + 288];
                const uint32_t al2 = ALO[rb + 4], al3 = ALO[rb + 292];
                mma_bf16(acc[i], ah0, ah1, ah2, ah3, bh0, bh1);
                mma_bf16(acc[i], ah0, ah1, ah2, ah3, bl0, bl1);
                mma_bf16(acc[i], al0, al1, al2, al3, bh0, bh1);
            }
        }
        __syncthreads();
    }

    // dump accs to S[112][68] (overlaying A staging — barrier above protects)
    #pragma unroll
    for (int i = 0; i < 7; i++) {
        const int cc = warp * 8 + 2 * t;
        *(float2*)(S + (i * 16 + g) * 68 + cc)     = make_float2(acc[i][0], acc[i][1]);
        *(float2*)(S + (i * 16 + g + 8) * 68 + cc) = make_float2(acc[i][2], acc[i][3]);
    }
    __syncthreads();

    // normalize slab row tid (<100) = logical chunk n = tid*8 + cb
    if (tid < LEN) {
        const float* Sr = S + tid * 68;
        float ss = 0.0f;
        #pragma unroll
        for (int u = 0; u < 16; u++) {
            float4 xv = *(const float4*)(Sr + u * 4);
            ss += xv.x * xv.x + xv.y * xv.y + xv.z * xv.z + xv.w * xv.w;
        }
        const float inv = 1.0f / fmaxf(sqrtf(ss), 1e-12f);
        const int n = tid * 8 + cb;               // raw-view chunk number
        const int hh = n / 100, ll = n % 100;     // logical head, position
        const uint32_t base = ((uint32_t)(b * 8 + hh) * 128 + ll) * 32;
        #pragma unroll
        for (int u = 0; u < 16; u++) {
            float4 xv = *(const float4*)(Sr + u * 4);
            uint32_t h0, l0, h1, l1;
            split2(xv.x * inv, xv.y * inv, h0, l0);
            split2(xv.z * inv, xv.w * inv, h1, l1);
            GH[base + u * 2] = h0; GH[base + u * 2 + 1] = h1;
            GL[base + u * 2] = l0; GL[base + u * 2 + 1] = l1;
        }
    }
}

// ---------------------------------------------------------------------------
// Kernel 2: build V^T hi/lo smem images in gmem. One block per (kb,h).
// V chunks are flat (raw view), so vp + m*64 + d indexing is already correct.
// ---------------------------------------------------------------------------
__global__ __launch_bounds__(256) void vimg_kernel(const float* __restrict__ v)
{
    __shared__ uint32_t sh[64 * 60], sl[64 * 60];
    const int bh = blockIdx.x;
    const int kb = bh >> 3, h = bh & 7;
    const float* vp = v + (size_t)kb * 51200 + h * 6400;
    const int tid = threadIdx.x;

    for (int e = tid; e < 64 * 60; e += 256) { sh[e] = 0u; sl[e] = 0u; }
    __syncthreads();
    for (int e = tid; e < 64 * 56; e += 256) {
        const int w = e >> 6, d = e & 63;
        const int m0 = 2 * w, m1 = 2 * w + 1;
        float x0 = (m0 < LEN) ? vp[m0 * 64 + d] : 0.0f;
        float x1 = (m1 < LEN) ? vp[m1 * 64 + d] : 0.0f;
        uint32_t hw, lw;
        split2(x0, x1, hw, lw);
        sh[d * 60 + w] = hw;
        sl[d * 60 + w] = lw;
    }
    __syncthreads();
    uint4* GH = (uint4*)(g_Vhi + (size_t)bh * 3840);
    uint4* GL = (uint4*)(g_Vlo + (size_t)bh * 3840);
    const uint4* SH = (const uint4*)sh;
    const uint4* SL = (const uint4*)sl;
    for (int e = tid; e < 960; e += 256) { GH[e] = SH[e]; GL[e] = SL[e]; }
}

// ---------------------------------------------------------------------------
// Kernel 3: attention per (qb,kb,h), 8 warps, M=112.
// S[112x112] = Q K^T : 98 m16n8 tiles dealt t==warp (mod 8), 12 mma each.
// P = exp(20*relu(S)) masked -> smem hi/lo (overlays Q/K). Rowsums: smem atomics.
// O[112x64] = P V : warp w owns n8-strip w, 7 m16 tiles, 21 mma each.
// ---------------------------------------------------------------------------
#define OFF_RS   0                       // 112 floats (512B padded)
#define OFF_QHI  512                     // 112 x 36 words = 16128B each
#define OFF_QLO  16640
#define OFF_KHI  32768
#define OFF_KLO  48896                   // end 65024
#define OFF_VHI  65024                   // 64 x 60 words = 15360B each
#define OFF_VLO  80384                   // end 95744
#define OFF_PHI  512                     // overlays Q/K: 112 x 60 words = 26880B
#define OFF_PLO  27392                   // end 54272 < 65024
#define ATTN_SMEM 95744                  // -> 2 CTAs/SM

__global__ __launch_bounds__(256, 2) void attn_kernel(float* __restrict__ out)
{
    extern __shared__ char sm[];
    float* RS = (float*)(sm + OFF_RS);
    uint32_t* QHI = (uint32_t*)(sm + OFF_QHI);
    uint32_t* QLO = (uint32_t*)(sm + OFF_QLO);
    uint32_t* KHI = (uint32_t*)(sm + OFF_KHI);
    uint32_t* KLO = (uint32_t*)(sm + OFF_KLO);
    uint32_t* VHI = (uint32_t*)(sm + OFF_VHI);
    uint32_t* VLO = (uint32_t*)(sm + OFF_VLO);
    uint32_t* PHI = (uint32_t*)(sm + OFF_PHI);
    uint32_t* PLO = (uint32_t*)(sm + OFF_PLO);

    const int bx = blockIdx.x;
    const int h  = bx & 7;
    const int qb = (bx >> 3) & 31;
    const int kb = bx >> 8;
    const int tid = threadIdx.x;
    const int warp = tid >> 5, lane = tid & 31;
    const int g = lane >> 2, t = lane & 3;

    // ---- staging: pure uint4 copies from pre-built gmem images
    {
        const uint4* sqh = (const uint4*)(g_Qhi + (size_t)(qb * 8 + h) * 4096);
        const uint4* sql = (const uint4*)(g_Qlo + (size_t)(qb * 8 + h) * 4096);
        const uint4* skh = (const uint4*)(g_Khi + (size_t)(kb * 8 + h) * 4096);
        const uint4* skl = (const uint4*)(g_Klo + (size_t)(kb * 8 + h) * 4096);
        uint4* dqh = (uint4*)QHI; uint4* dql = (uint4*)QLO;
        uint4* dkh = (uint4*)KHI; uint4* dkl = (uint4*)KLO;
        for (int i = tid; i < 896; i += 256) {        // 112 rows x 8 uint4
            const int r = i >> 3, c = i & 7;
            const int s = r * 8 + c, d = r * 9 + c;   // gmem stride 32w, smem 36w
            dqh[d] = sqh[s]; dql[d] = sql[s];
            dkh[d] = skh[s]; dkl[d] = skl[s];
        }
        const uint4* svh = (const uint4*)(g_Vhi + (size_t)(kb * 8 + h) * 3840);
        const uint4* svl = (const uint4*)(g_Vlo + (size_t)(kb * 8 + h) * 3840);
        uint4* dvh = (uint4*)VHI; uint4* dvl = (uint4*)VLO;
        for (int i = tid; i < 960; i += 256) { dvh[i] = svh[i]; dvl[i] = svl[i]; }
        if (tid < 112) RS[tid] = 0.0f;
    }
    __syncthreads();

    // ---- S phase: flattened tiles t == warp (mod 8), 98 tiles total
    float acc[13][4] = {};
    #pragma unroll
    for (int idx = 0; idx < 13; idx++) {
        const int tt = warp + idx * 8;
        if (tt < 98) {
            const int i = tt / 14, j = tt % 14;
            #pragma unroll
            for (int ks = 0; ks < 4; ks++) {
                const int rb = (i * 16 + g) * 36 + ks * 8 + t;
                const uint32_t ah0 = QHI[rb], ah1 = QHI[rb + 288];
                const uint32_t ah2 = QHI[rb + 4], ah3 = QHI[rb + 292];
                const uint32_t al0 = QLO[rb], al1 = QLO[rb + 288];
                const uint32_t al2 = QLO[rb + 4], al3 = QLO[rb + 292];
                const int nb = (j * 8 + g) * 36 + ks * 8 + t;
                const uint32_t bh0 = KHI[nb], bh1 = KHI[nb + 4];
                const uint32_t bl0 = KLO[nb], bl1 = KLO[nb + 4];
                mma_bf16(acc[idx], ah0, ah1, ah2, ah3, bh0, bh1);
                mma_bf16(acc[idx], ah0, ah1, ah2, ah3, bl0, bl1);
                mma_bf16(acc[idx], al0, al1, al2, al3, bh0, bh1);
            }
        }
    }
    __syncthreads();   // all Q/K reads done before P overlays them

    // ---- epilogue: exp, mask, rowsum atomics, split-store P
    #pragma unroll
    for (int idx = 0; idx < 13; idx++) {
        const int tt = warp + idx * 8;
        if (tt < 98) {
            const int i = tt / 14, j = tt % 14;
            const int col = j * 8 + 2 * t;
            float e0 = __expf(TEMP * fmaxf(acc[idx][0], 0.f));
            float e1 = __expf(TEMP * fmaxf(acc[idx][1], 0.f));
            float e2 = __expf(TEMP * fmaxf(acc[idx][2], 0.f));
            float e3 = __expf(TEMP * fmaxf(acc[idx][3], 0.f));
            if (col     >= LEN) { e0 = 0.f; e2 = 0.f; }
            if (col + 1 >= LEN) { e1 = 0.f; e3 = 0.f; }
            float p0 = e0 + e1, p1 = e2 + e3;
            p0 += __shfl_xor_sync(0xffffffffu, p0, 1);
            p0 += __shfl_xor_sync(0xffffffffu, p0, 2);
            p1 += __shfl_xor_sync(0xffffffffu, p1, 1);
            p1 += __shfl_xor_sync(0xffffffffu, p1, 2);
            if (t == 0) {
                atomicAdd(&RS[i * 16 + g], p0);
                atomicAdd(&RS[i * 16 + g + 8], p1);
            }
            const int w0 = (i * 16 + g) * 60 + j * 4 + t;
            uint32_t ph, pl;
            split2(e0, e1, ph, pl);
            PHI[w0] = ph;       PLO[w0] = pl;
            split2(e2, e3, ph, pl);
            PHI[w0 + 480] = ph; PLO[w0 + 480] = pl;
        }
    }
    __syncthreads();

    // ---- O phase: warp = n8-strip j, i = 0..6, K = 112 (7 k-steps)
    const size_t ob = (size_t)(kb * 32 + qb) * LEN * DMODEL + h * 64;
    #pragma unroll
    for (int i = 0; i < 7; i++) {
        const int j = warp;
        float c4[4] = {0.f, 0.f, 0.f, 0.f};
        #pragma unroll
        for (int ks = 0; ks < 7; ks++) {
            const int rb = (i * 16 + g) * 60 + ks * 8 + t;
            const uint32_t ah0 = PHI[rb], ah1 = PHI[rb + 480];
            const uint32_t ah2 = PHI[rb + 4], ah3 = PHI[rb + 484];
            const uint32_t al0 = PLO[rb], al1 = PLO[rb + 480];
            const uint32_t al2 = PLO[rb + 4], al3 = PLO[rb + 484];
            const int nb = (j * 8 + g) * 60 + ks * 8 + t;
            const uint32_t bh0 = VHI[nb], bh1 = VHI[nb + 4];
            const uint32_t bl0 = VLO[nb], bl1 = VLO[nb + 4];
            mma_bf16(c4, ah0, ah1, ah2, ah3, bh0, bh1);
            mma_bf16(c4, ah0, ah1, ah2, ah3, bl0, bl1);
            mma_bf16(c4, al0, al1, al2, al3, bh0, bh1);
        }
        const int r0 = i * 16 + g;
        const int cc = j * 8 + 2 * t;
        if (r0 < LEN) {
            const float inv = 1.0f / RS[r0];
            *(float2*)(out + ob + (size_t)r0 * DMODEL + cc) =
                make_float2(c4[0] * inv, c4[1] * inv);
        }
        if (r0 + 8 < LEN) {
            const float inv = 1.0f / RS[r0 + 8];
            *(float2*)(out + ob + (size_t)(r0 + 8) * DMODEL + cc) =
                make_float2(c4[2] * inv, c4[3] * inv);
        }
    }
}

// ---------------------------------------------------------------------------
extern "C" void kernel_launch(void* const* d_in, const int* in_sizes, int n_in,
                              void* d_out, int out_size)
{
    const float* q    = (const float*)d_in[0];
    const float* k    = (const float*)d_in[1];
    const float* v    = (const float*)d_in[2];
    const float* w_qs = (const float*)d_in[3];
    const float* w_ks = (const float*)d_in[4];
    float* out = (float*)d_out;

    cudaFuncSetAttribute(proj_kernel,
                         cudaFuncAttributeMaxDynamicSharedMemorySize, PJ_SMEM);
    cudaFuncSetAttribute(attn_kernel,
                         cudaFuncAttributeMaxDynamicSharedMemorySize, ATTN_SMEM);

    proj_kernel<<<dim3(8, 32, 2), 256, PJ_SMEM>>>(q, k, w_qs, w_ks);
    vimg_kernel<<<256, 256>>>(v);
    attn_kernel<<<8192, 256, ATTN_SMEM>>>(out);
}

// round 7
// speedup vs baseline: 1.7794x; 1.7794x over previous
#include <cuda_runtime.h>
#include <cuda_fp16.h>
#include <cstdint>

// Problem constants
#define NHEAD   8
#define DK      64
#define LEN     100
#define BS      32
#define DMODEL  512
#define TEMP    20.0f
#define LN8192  9.0109133f

// Pre-split normalized projections (fp16 hi/lo): [b][h][128 rows][64] packed as
// 32 u32 words/row. Rows 100..127 never written -> stay zero = free padding.
__device__ __align__(16) uint32_t g_Qhi[BS * NHEAD * 128 * 32];
__device__ __align__(16) uint32_t g_Qlo[BS * NHEAD * 128 * 32];
__device__ __align__(16) uint32_t g_Khi[BS * NHEAD * 128 * 32];
__device__ __align__(16) uint32_t g_Klo[BS * NHEAD * 128 * 32];
// V^T images per (kb,h): 64 d-rows x 60 words (fp16 pairs, m pairs 0..111,
// m>=100 zero, words 56..59 pad). Exactly the smem image attn wants.
__device__ __align__(16) uint32_t g_Vhi[BS * NHEAD * 64 * 60];
__device__ __align__(16) uint32_t g_Vlo[BS * NHEAD * 64 * 60];

// ---------------------------------------------------------------------------
__device__ __forceinline__ void mma_f16(float c[4],
    uint32_t a0, uint32_t a1, uint32_t a2, uint32_t a3,
    uint32_t b0, uint32_t b1)
{
    asm volatile(
        "mma.sync.aligned.m16n8k16.row.col.f32.f16.f16.f32 "
        "{%0,%1,%2,%3}, {%4,%5,%6,%7}, {%8,%9}, {%0,%1,%2,%3};"
        : "+f"(c[0]), "+f"(c[1]), "+f"(c[2]), "+f"(c[3])
        : "r"(a0), "r"(a1), "r"(a2), "r"(a3), "r"(b0), "r"(b1));
}

__device__ __forceinline__ void split2h(float x0, float x1,
                                        uint32_t& hi, uint32_t& lo)
{
    __half2 h = __floats2half2_rn(x0, x1);
    float2 hf = __half22float2(h);
    __half2 l = __floats2half2_rn(x0 - hf.x, x1 - hf.y);
    hi = *(uint32_t*)&h;
    lo = *(uint32_t*)&l;
}

// ---------------------------------------------------------------------------
// Kernel 1: projection via fp16 3-term mma + fused L2-norm, pre-split output.
// Block = (cb, b, sel): P rows b*100..+99 (pad 112), cols cb*64..+63, K=512.
// Raw-view head mapping: slab row r, band cb -> chunk n = r*8 + cb,
// h = n/100, l = n%100. Register-prefetch double buffering hides gmem latency.
// ---------------------------------------------------------------------------
#define PJ_AHI 0                    // 112 x 36 words
#define PJ_ALO 16128
#define PJ_BHI 32256                // 64 x 36 words
#define PJ_BLO 41472
#define PJ_SMEM 50688               // S[112][68] fp32 overlays A after mma

__global__ __launch_bounds__(256) void proj_kernel(
    const float* __restrict__ q, const float* __restrict__ k,
    const float* __restrict__ w_qs, const float* __restrict__ w_ks)
{
    extern __shared__ char sm[];
    uint32_t* AHI = (uint32_t*)(sm + PJ_AHI);
    uint32_t* ALO = (uint32_t*)(sm + PJ_ALO);
    uint32_t* BHI = (uint32_t*)(sm + PJ_BHI);
    uint32_t* BLO = (uint32_t*)(sm + PJ_BLO);
    float* S = (float*)sm;

    const int cb = blockIdx.x, b = blockIdx.y, sel = blockIdx.z;
    const float* x = sel ? k : q;
    const float* w = sel ? w_ks : w_qs;
    uint32_t* GH = sel ? g_Khi : g_Qhi;
    uint32_t* GL = sel ? g_Klo : g_Qlo;

    const int tid = threadIdx.x;
    const int warp = tid >> 5, lane = tid & 31;
    const int g = lane >> 2, t = lane & 3;

    float4 pa[7], pb[4];

    // prefetch chunk 0
    #pragma unroll
    for (int u = 0; u < 7; u++) {
        const int i = tid + 256 * u, r = i >> 4, c4 = i & 15;
        pa[u] = (r < LEN)
            ? *(const float4*)(x + (size_t)(b * 100 + r) * DMODEL + c4 * 4)
            : make_float4(0.f, 0.f, 0.f, 0.f);
    }
    #pragma unroll
    for (int u = 0; u < 4; u++) {
        const int i = tid + 256 * u, r = i >> 4, c4 = i & 15;
        pb[u] = *(const float4*)(w + (size_t)(cb * 64 + r) * DMODEL + c4 * 4);
    }

    float acc[7][4] = {};

    for (int c = 0; c < 8; c++) {
        __syncthreads();          // prior chunk's mma done reading smem
        // store prefetched regs (split to fp16 hi/lo)
        #pragma unroll
        for (int u = 0; u < 7; u++) {
            const int i = tid + 256 * u, r = i >> 4, c4 = i & 15;
            uint32_t h0, l0, h1, l1;
            split2h(pa[u].x, pa[u].y, h0, l0);
            split2h(pa[u].z, pa[u].w, h1, l1);
            AHI[r * 36 + c4 * 2] = h0; AHI[r * 36 + c4 * 2 + 1] = h1;
            ALO[r * 36 + c4 * 2] = l0; ALO[r * 36 + c4 * 2 + 1] = l1;
        }
        #pragma unroll
        for (int u = 0; u < 4; u++) {
            const int i = tid + 256 * u, r = i >> 4, c4 = i & 15;
            uint32_t h0, l0, h1, l1;
            split2h(pb[u].x, pb[u].y, h0, l0);
            split2h(pb[u].z, pb[u].w, h1, l1);
            BHI[r * 36 + c4 * 2] = h0; BHI[r * 36 + c4 * 2 + 1] = h1;
            BLO[r * 36 + c4 * 2] = l0; BLO[r * 36 + c4 * 2 + 1] = l1;
        }
        __syncthreads();
        // issue prefetch for chunk c+1 (consumed next iteration)
        if (c < 7) {
            const int k0 = (c + 1) * 64;
            #pragma unroll
            for (int u = 0; u < 7; u++) {
                const int i = tid + 256 * u, r = i >> 4, c4 = i & 15;
                pa[u] = (r < LEN)
                    ? *(const float4*)(x + (size_t)(b * 100 + r) * DMODEL + k0 + c4 * 4)
                    : make_float4(0.f, 0.f, 0.f, 0.f);
            }
            #pragma unroll
            for (int u = 0; u < 4; u++) {
                const int i = tid + 256 * u, r = i >> 4, c4 = i & 15;
                pb[u] = *(const float4*)(w + (size_t)(cb * 64 + r) * DMODEL + k0 + c4 * 4);
            }
        }
        // mma on current chunk
        #pragma unroll
        for (int ks = 0; ks < 4; ks++) {
            const int nb = (warp * 8 + g) * 36 + ks * 8 + t;
            const uint32_t bh0 = BHI[nb], bh1 = BHI[nb + 4];
            const uint32_t bl0 = BLO[nb], bl1 = BLO[nb + 4];
            #pragma unroll
            for (int i = 0; i < 7; i++) {
                const int rb = (i * 16 + g) * 36 + ks * 8 + t;
                const uint32_t ah0 = AHI[rb], ah1 = AHI[rb + 288];
                const uint32_t ah2 = AHI[rb + 4], ah3 = AHI[rb + 292];
                const uint32_t al0 = ALO[rb], al1 = ALO[rb + 288];
                const uint32_t al2 = ALO[rb + 4], al3 = ALO[rb + 292];
                mma_f16(acc[i], ah0, ah1, ah2, ah3, bh0, bh1);
                mma_f16(acc[i], ah0, ah1, ah2, ah3, bl0, bl1);
                mma_f16(acc[i], al0, al1, al2, al3, bh0, bh1);
            }
        }
    }
    __syncthreads();

    // dump accs to S[112][68] (overlays A staging)
    #pragma unroll
    for (int i = 0; i < 7; i++) {
        const int cc = warp * 8 + 2 * t;
        *(float2*)(S + (i * 16 + g) * 68 + cc)     = make_float2(acc[i][0], acc[i][1]);
        *(float2*)(S + (i * 16 + g + 8) * 68 + cc) = make_float2(acc[i][2], acc[i][3]);
    }
    __syncthreads();

    // normalize slab row tid (<100) = raw-view chunk n = tid*8 + cb
    if (tid < LEN) {
        const float* Sr = S + tid * 68;
        float ss = 0.0f;
        #pragma unroll
        for (int u = 0; u < 16; u++) {
            float4 xv = *(const float4*)(Sr + u * 4);
            ss += xv.x * xv.x + xv.y * xv.y + xv.z * xv.z + xv.w * xv.w;
        }
        const float inv = 1.0f / fmaxf(sqrtf(ss), 1e-12f);
        const int n = tid * 8 + cb;
        const int hh = n / 100, ll = n % 100;
        const uint32_t base = ((uint32_t)(b * 8 + hh) * 128 + ll) * 32;
        #pragma unroll
        for (int u = 0; u < 16; u++) {
            float4 xv = *(const float4*)(Sr + u * 4);
            uint32_t h0, l0, h1, l1;
            split2h(xv.x * inv, xv.y * inv, h0, l0);
            split2h(xv.z * inv, xv.w * inv, h1, l1);
            GH[base + u * 2] = h0; GH[base + u * 2 + 1] = h1;
            GL[base + u * 2] = l0; GL[base + u * 2 + 1] = l1;
        }
    }
}

// ---------------------------------------------------------------------------
// Kernel 2: build V^T fp16 hi/lo smem images in gmem. One block per (kb,h).
// ---------------------------------------------------------------------------
__global__ __launch_bounds__(256) void vimg_kernel(const float* __restrict__ v)
{
    __shared__ uint32_t sh[64 * 60], sl[64 * 60];
    const int bh = blockIdx.x;
    const int kb = bh >> 3, h = bh & 7;
    const float* vp = v + (size_t)kb * 51200 + h * 6400;
    const int tid = threadIdx.x;

    for (int e = tid; e < 64 * 60; e += 256) { sh[e] = 0u; sl[e] = 0u; }
    __syncthreads();
    for (int e = tid; e < 64 * 56; e += 256) {
        const int w = e >> 6, d = e & 63;
        const int m0 = 2 * w, m1 = 2 * w + 1;
        float x0 = (m0 < LEN) ? vp[m0 * 64 + d] : 0.0f;
        float x1 = (m1 < LEN) ? vp[m1 * 64 + d] : 0.0f;
        uint32_t hw, lw;
        split2h(x0, x1, hw, lw);
        sh[d * 60 + w] = hw;
        sl[d * 60 + w] = lw;
    }
    __syncthreads();
    uint4* GH = (uint4*)(g_Vhi + (size_t)bh * 3840);
    uint4* GL = (uint4*)(g_Vlo + (size_t)bh * 3840);
    const uint4* SH = (const uint4*)sh;
    const uint4* SL = (const uint4*)sl;
    for (int e = tid; e < 960; e += 256) { GH[e] = SH[e]; GL[e] = SL[e]; }
}

// ---------------------------------------------------------------------------
// Kernel 3: attention per (qb,kb,h), 8 warps, round-2 structure, fp16.
//   S[128x112] = Q K^T   (3-term fp16; warps 4M x 2N; wn=1 skips dead strip)
//   P = exp(20*relu(S) - ln8192) masked, single fp16, overlays Q smem
//   O[128x64]  = P V     (2-term: P*Vhi + P*Vlo)
// Rowsums from the ROUNDED fp16 P (common-mode rounding cancels in divide).
// ---------------------------------------------------------------------------
#define OFF_RS   0                       // 128 rows x 2 floats = 1024B
#define OFF_QHI  1024                    // 128 x 36 words = 18432B
#define OFF_QLO  19456                   // 128 x 36 words
#define OFF_KHI  37888                   // 112 x 36 words = 16128B
#define OFF_KLO  54016
#define OFF_VHI  70144                   // 64 x 60 words = 15360B
#define OFF_VLO  85504
#define ATTN_SMEM 100864                 // -> 2 CTAs/SM
#define OFF_P    1024                    // overlays QHI/QLO: 128 x 60 w = 30720B

__global__ __launch_bounds__(256, 2) void attn_kernel(float* __restrict__ out)
{
    extern __shared__ char sm[];
    float* RS = (float*)(sm + OFF_RS);
    uint32_t* QHI = (uint32_t*)(sm + OFF_QHI);
    uint32_t* QLO = (uint32_t*)(sm + OFF_QLO);
    uint32_t* KHI = (uint32_t*)(sm + OFF_KHI);
    uint32_t* KLO = (uint32_t*)(sm + OFF_KLO);
    uint32_t* VHI = (uint32_t*)(sm + OFF_VHI);
    uint32_t* VLO = (uint32_t*)(sm + OFF_VLO);
    uint32_t* P   = (uint32_t*)(sm + OFF_P);

    const int bx = blockIdx.x;
    const int h  = bx & 7;
    const int qb = (bx >> 3) & 31;
    const int kb = bx >> 8;
    const int tid = threadIdx.x;
    const int warp = tid >> 5, lane = tid & 31;
    const int g = lane >> 2, t = lane & 3;

    // ---- staging: pure uint4 copies from pre-built gmem images
    {
        const uint4* sqh = (const uint4*)(g_Qhi + (size_t)(qb * 8 + h) * 4096);
        const uint4* sql = (const uint4*)(g_Qlo + (size_t)(qb * 8 + h) * 4096);
        uint4* dqh = (uint4*)QHI; uint4* dql = (uint4*)QLO;
        for (int i = tid; i < 1024; i += 256) {       // Q: 128 rows x 8 uint4
            const int r = i >> 3, c = i & 7;
            const int s = r * 8 + c, d = r * 9 + c;
            dqh[d] = sqh[s]; dql[d] = sql[s];
        }
        const uint4* skh = (const uint4*)(g_Khi + (size_t)(kb * 8 + h) * 4096);
        const uint4* skl = (const uint4*)(g_Klo + (size_t)(kb * 8 + h) * 4096);
        uint4* dkh = (uint4*)KHI; uint4* dkl = (uint4*)KLO;
        for (int i = tid; i < 896; i += 256) {        // K: 112 rows x 8 uint4
            const int r = i >> 3, c = i & 7;
            const int s = r * 8 + c, d = r * 9 + c;
            dkh[d] = skh[s]; dkl[d] = skl[s];
        }
        const uint4* svh = (const uint4*)(g_Vhi + (size_t)(kb * 8 + h) * 3840);
        const uint4* svl = (const uint4*)(g_Vlo + (size_t)(kb * 8 + h) * 3840);
        uint4* dvh = (uint4*)VHI; uint4* dvl = (uint4*)VLO;
        for (int i = tid; i < 960; i += 256) { dvh[i] = svh[i]; dvl[i] = svl[i]; }
    }
    __syncthreads();

    const int wm = warp & 3, wn = warp >> 2;
    const int r0 = wm * 32;
    const int c0 = wn * 56;

    // ---- S phase: warp computes rows [r0,r0+32) x cols [c0,c0+56)
    // wn=1 skips j=6 (cols 104..111 entirely masked).
    float acc[2][7][4] = {};
    #pragma unroll
    for (int ks = 0; ks < 4; ks++) {
        uint32_t ah[2][4], al[2][4];
        #pragma unroll
        for (int i = 0; i < 2; i++) {
            const int rb = (r0 + 16 * i + g) * 36 + ks * 8 + t;
            ah[i][0] = QHI[rb];        al[i][0] = QLO[rb];
            ah[i][1] = QHI[rb + 288];  al[i][1] = QLO[rb + 288];
            ah[i][2] = QHI[rb + 4];    al[i][2] = QLO[rb + 4];
            ah[i][3] = QHI[rb + 292];  al[i][3] = QLO[rb + 292];
        }
        #pragma unroll
        for (int j = 0; j < 7; j++) {
            if (wn == 0 || j < 6) {
                const int nb = (c0 + 8 * j + g) * 36 + ks * 8 + t;
                const uint32_t bh0 = KHI[nb], bh1 = KHI[nb + 4];
                const uint32_t bl0 = KLO[nb], bl1 = KLO[nb + 4];
                #pragma unroll
                for (int i = 0; i < 2; i++) {
                    mma_f16(acc[i][j], ah[i][0], ah[i][1], ah[i][2], ah[i][3], bh0, bh1);
                    mma_f16(acc[i][j], ah[i][0], ah[i][1], ah[i][2], ah[i][3], bl0, bl1);
                    mma_f16(acc[i][j], al[i][0], al[i][1], al[i][2], al[i][3], bh0, bh1);
                }
            }
        }
    }
    __syncthreads();   // all Q reads done before P overlays Q smem

    // ---- epilogue: e = exp(20*relu(s) - ln8192), mask, pack fp16, rowsums
    {
        #pragma unroll
        for (int i = 0; i < 2; i++) {
            float rsg = 0.0f, rsg8 = 0.0f;
            #pragma unroll
            for (int j = 0; j < 7; j++) {
                const int col = c0 + 8 * j + 2 * t;
                const bool dead = (wn == 1 && j == 6);
                float e0 = 0.f, e1 = 0.f, e2 = 0.f, e3 = 0.f;
                if (!dead) {
                    e0 = __expf(fmaf(TEMP, fmaxf(acc[i][j][0], 0.f), -LN8192));
                    e1 = __expf(fmaf(TEMP, fmaxf(acc[i][j][1], 0.f), -LN8192));
                    e2 = __expf(fmaf(TEMP, fmaxf(acc[i][j][2], 0.f), -LN8192));
                    e3 = __expf(fmaf(TEMP, fmaxf(acc[i][j][3], 0.f), -LN8192));
                    if (col     >= LEN) { e0 = 0.f; e2 = 0.f; }
                    if (col + 1 >= LEN) { e1 = 0.f; e3 = 0.f; }
                }
                __half2 h01 = __floats2half2_rn(e0, e1);
                __half2 h23 = __floats2half2_rn(e2, e3);
                float2 f01 = __half22float2(h01);
                float2 f23 = __half22float2(h23);
                rsg  += f01.x + f01.y;
                rsg8 += f23.x + f23.y;
                const int w0 = (r0 + 16 * i + g) * 60 + (c0 >> 1) + j * 4 + t;
                P[w0]       = *(uint32_t*)&h01;
                P[w0 + 480] = *(uint32_t*)&h23;
            }
            rsg  += __shfl_xor_sync(0xffffffffu, rsg, 1);
            rsg  += __shfl_xor_sync(0xffffffffu, rsg, 2);
            rsg8 += __shfl_xor_sync(0xffffffffu, rsg8, 1);
            rsg8 += __shfl_xor_sync(0xffffffffu, rsg8, 2);
            if (t == 0) {
                RS[(r0 + 16 * i + g) * 2 + wn]     = rsg;
                RS[(r0 + 16 * i + g + 8) * 2 + wn] = rsg8;
            }
        }
    }
    __syncthreads();

    // ---- O phase: warp rows [r0,r0+32) x dv cols [wn*32, wn*32+32), K=112
    float o[2][4][4] = {};
    #pragma unroll
    for (int ks = 0; ks < 7; ks++) {
        uint32_t a[2][4];
        #pragma unroll
        for (int i = 0; i < 2; i++) {
            const int rb = (r0 + 16 * i + g) * 60 + ks * 8 + t;
            a[i][0] = P[rb];        a[i][1] = P[rb + 480];
            a[i][2] = P[rb + 4];    a[i][3] = P[rb + 484];
        }
        #pragma unroll
        for (int j = 0; j < 4; j++) {
            const int nb = (wn * 32 + 8 * j + g) * 60 + ks * 8 + t;
            const uint32_t bh0 = VHI[nb], bh1 = VHI[nb + 4];
            const uint32_t bl0 = VLO[nb], bl1 = VLO[nb + 4];
            #pragma unroll
            for (int i = 0; i < 2; i++) {
                mma_f16(o[i][j], a[i][0], a[i][1], a[i][2], a[i][3], bh0, bh1);
                mma_f16(o[i][j], a[i][0], a[i][1], a[i][2], a[i][3], bl0, bl1);
            }
        }
    }

    // ---- output: divide by rowsum, write [kb][qb][l][h*64+d]
    const size_t ob = (size_t)(kb * 32 + qb) * LEN * DMODEL + h * 64;
    #pragma unroll
    for (int i = 0; i < 2; i++) {
        const int r = r0 + 16 * i + g;
        float inv0 = 0.f, inv1 = 0.f;
        if (r < LEN)     inv0 = 1.0f / (RS[r * 2] + RS[r * 2 + 1]);
        if (r + 8 < LEN) inv1 = 1.0f / (RS[(r + 8) * 2] + RS[(r + 8) * 2 + 1]);
        #pragma unroll
        for (int j = 0; j < 4; j++) {
            const int cc = wn * 32 + 8 * j + 2 * t;
            if (r < LEN) {
                *(float2*)(out + ob + (size_t)r * DMODEL + cc) =
                    make_float2(o[i][j][0] * inv0, o[i][j][1] * inv0);
            }
            if (r + 8 < LEN) {
                *(float2*)(out + ob + (size_t)(r + 8) * DMODEL + cc) =
                    make_float2(o[i][j][2] * inv1, o[i][j][3] * inv1);
            }
        }
    }
}

// ---------------------------------------------------------------------------
extern "C" void kernel_launch(void* const* d_in, const int* in_sizes, int n_in,
                              void* d_out, int out_size)
{
    const float* q    = (const float*)d_in[0];
    const float* k    = (const float*)d_in[1];
    const float* v    = (const float*)d_in[2];
    const float* w_qs = (const float*)d_in[3];
    const float* w_ks = (const float*)d_in[4];
    float* out = (float*)d_out;

    cudaFuncSetAttribute(proj_kernel,
                         cudaFuncAttributeMaxDynamicSharedMemorySize, PJ_SMEM);
    cudaFuncSetAttribute(attn_kernel,
                         cudaFuncAttributeMaxDynamicSharedMemorySize, ATTN_SMEM);

    proj_kernel<<<dim3(8, 32, 2), 256, PJ_SMEM>>>(q, k, w_qs, w_ks);
    vimg_kernel<<<256, 256>>>(v);
    attn_kernel<<<8192, 256, ATTN_SMEM>>>(out);
}